// round 1
// baseline (speedup 1.0000x reference)
#include <cuda_runtime.h>

#define NN 20000
#define EE 320000
#define DD 128
#define KK 8
#define HH 64
#define KH 512   // K*H

// ---------------- scratch (static device arrays; no runtime allocation) ----
__device__ float g_mean[(size_t)EE * DD];     // 164 MB : mean over metapath
__device__ float g_ft[(size_t)EE * KH];       // 655 MB : encoded edge features
__device__ float g_ex[(size_t)EE * KK];       // 10 MB  : exp(logits)
__device__ float g_er[(size_t)NN * KK];       // er = node_feat @ W_r^T
__device__ float g_segsum[(size_t)NN * KK];   // softmax denominators

// ---------------- zero out + segsum ----------------------------------------
__global__ void zero_kernel(float* __restrict__ out) {
    int stride = gridDim.x * blockDim.x;
    int i = blockIdx.x * blockDim.x + threadIdx.x;
    for (int t = i; t < NN * KH; t += stride) out[t] = 0.0f;
    for (int t = i; t < NN * KK; t += stride) g_segsum[t] = 0.0f;
}

// ---------------- er[n][k] = dot(node_feat[n], W_r[k]) ---------------------
// one warp per node; each lane holds 4 dims of the node row
__global__ void er_kernel(const float* __restrict__ nf, const float* __restrict__ Wr) {
    int warp = (blockIdx.x * blockDim.x + threadIdx.x) >> 5;
    int lane = threadIdx.x & 31;
    if (warp >= NN) return;
    float4 x = *(const float4*)(nf + (size_t)warp * DD + lane * 4);
#pragma unroll
    for (int k = 0; k < KK; k++) {
        float4 w = *(const float4*)(Wr + (size_t)k * DD + lane * 4);
        float p = x.x * w.x + x.y * w.y + x.z * w.z + x.w * w.w;
#pragma unroll
        for (int off = 16; off > 0; off >>= 1) p += __shfl_xor_sync(0xffffffffu, p, off);
        if (lane == 0) g_er[(size_t)warp * KK + k] = p;
    }
}

// ---------------- m = mean(edge_feat over L=3) ------------------------------
__global__ void mean_kernel(const float4* __restrict__ ef4) {
    int t = blockIdx.x * blockDim.x + threadIdx.x;   // one float4 of output
    if (t >= EE * (DD / 4)) return;
    int e = t >> 5;            // DD/4 = 32 float4s per edge row
    int c = t & 31;
    size_t base = (size_t)e * 96 + c;                // 3 * 32 float4 per edge
    float4 a = ef4[base], b = ef4[base + 32], d = ef4[base + 64];
    const float s = 1.0f / 3.0f;
    float4 m;
    m.x = (a.x + b.x + d.x) * s;
    m.y = (a.y + b.y + d.y) * s;
    m.z = (a.z + b.z + d.z) * s;
    m.w = (a.w + b.w + d.w) * s;
    ((float4*)g_mean)[t] = m;
}

// ---------------- ft = m @ W_enc  (fp32 tiled GEMM) -------------------------
// C (E x 512) = A (E x 128) * B (128 x 512)
// BM=128, BN=128, BK=16, 256 threads, 8x8 register microtile per thread.
#define BM 128
#define BN 128
#define BK 16
__global__ __launch_bounds__(256) void gemm_kernel(const float* __restrict__ B) {
    __shared__ float As[BK][BM];
    __shared__ float Bs[BK][BN];
    int bx = blockIdx.x;            // 0..3 over N=512
    int by = blockIdx.y;            // 0..2499 over E
    int t = threadIdx.x;
    int tx = t & 15;                // col group
    int ty = t >> 4;                // row group
    float acc[8][8];
#pragma unroll
    for (int i = 0; i < 8; i++)
#pragma unroll
        for (int j = 0; j < 8; j++) acc[i][j] = 0.0f;

    const float* Ab = g_mean + (size_t)by * BM * DD;
    const float* Bb = B + bx * BN;

    for (int k0 = 0; k0 < DD; k0 += BK) {
        // A tile: 128 rows x 16 cols -> transposed into As[k][m]
#pragma unroll
        for (int i = 0; i < 2; i++) {
            int idx = i * 256 + t;           // 0..511 float4 loads
            int r = idx >> 2;                // row 0..127
            int c4 = idx & 3;                // float4 within the 16 cols
            float4 v = *(const float4*)(Ab + (size_t)r * DD + k0 + c4 * 4);
            As[c4 * 4 + 0][r] = v.x;
            As[c4 * 4 + 1][r] = v.y;
            As[c4 * 4 + 2][r] = v.z;
            As[c4 * 4 + 3][r] = v.w;
        }
        // B tile: 16 rows x 128 cols
#pragma unroll
        for (int i = 0; i < 2; i++) {
            int idx = i * 256 + t;
            int r = idx >> 5;                // row 0..15
            int c4 = idx & 31;               // float4 col
            float4 v = *(const float4*)(Bb + (size_t)(k0 + r) * KH + c4 * 4);
            *(float4*)&Bs[r][c4 * 4] = v;
        }
        __syncthreads();
#pragma unroll
        for (int k = 0; k < BK; k++) {
            float a[8], b[8];
            *(float4*)&a[0] = *(const float4*)&As[k][ty * 8];
            *(float4*)&a[4] = *(const float4*)&As[k][ty * 8 + 4];
            *(float4*)&b[0] = *(const float4*)&Bs[k][tx * 8];
            *(float4*)&b[4] = *(const float4*)&Bs[k][tx * 8 + 4];
#pragma unroll
            for (int i = 0; i < 8; i++)
#pragma unroll
                for (int j = 0; j < 8; j++) acc[i][j] += a[i] * b[j];
        }
        __syncthreads();
    }
    // epilogue
#pragma unroll
    for (int i = 0; i < 8; i++) {
        size_t row = (size_t)(by * BM + ty * 8 + i) * KH + bx * BN + tx * 8;
        float4 v0 = make_float4(acc[i][0], acc[i][1], acc[i][2], acc[i][3]);
        float4 v1 = make_float4(acc[i][4], acc[i][5], acc[i][6], acc[i][7]);
        *(float4*)(g_ft + row) = v0;
        *(float4*)(g_ft + row + 4) = v1;
    }
}

// ---------------- logits + exp + segment denominators -----------------------
// one warp per edge; half-warps own alternating k slots per 128-col chunk
__global__ void logits_kernel(const float* __restrict__ attn_l,
                              const int* __restrict__ dst) {
    __shared__ float al[KH];
    __shared__ float el_s[8][KK];       // 8 warps per block
    for (int i = threadIdx.x; i < KH; i += blockDim.x) al[i] = attn_l[i];
    __syncthreads();

    int wg = (blockIdx.x * blockDim.x + threadIdx.x) >> 5;
    int lane = threadIdx.x & 31;
    int wl = (threadIdx.x >> 5) & 7;
    if (wg >= EE) return;

    const float* row = g_ft + (size_t)wg * KH;
    int d = dst[wg];
#pragma unroll
    for (int c = 0; c < 4; c++) {
        int pos = c * 128 + lane * 4;   // lanes 0-15 -> k=2c, lanes 16-31 -> k=2c+1
        float4 f = *(const float4*)(row + pos);
        float4 w = *(const float4*)(al + pos);
        float p = f.x * w.x + f.y * w.y + f.z * w.z + f.w * w.w;
#pragma unroll
        for (int off = 8; off > 0; off >>= 1) p += __shfl_xor_sync(0xffffffffu, p, off);
        if ((lane & 15) == 0) el_s[wl][c * 2 + (lane >> 4)] = p;
    }
    __syncwarp();
    if (lane < KK) {
        float v = el_s[wl][lane] + g_er[(size_t)d * KK + lane];
        v = (v > 0.0f) ? v : 0.01f * v;      // leaky relu
        float exv = expf(v);                  // shift-free softmax (bounded logits)
        g_ex[(size_t)wg * KK + lane] = exv;
        atomicAdd(&g_segsum[(size_t)d * KK + lane], exv);
    }
}

// ---------------- weighted scatter into destination nodes -------------------
__global__ void scatter_kernel(const int* __restrict__ dst, float* __restrict__ out) {
    int wg = (blockIdx.x * blockDim.x + threadIdx.x) >> 5;
    int lane = threadIdx.x & 31;
    if (wg >= EE) return;
    int d = dst[wg];
    const float* row = g_ft + (size_t)wg * KH;
    float* orow = out + (size_t)d * KH;
#pragma unroll
    for (int c = 0; c < 4; c++) {
        int k = c * 2 + (lane >> 4);
        float aval = g_ex[(size_t)wg * KK + k] / g_segsum[(size_t)d * KK + k];
        int pos = c * 128 + lane * 4;
        float4 f = *(const float4*)(row + pos);
        atomicAdd(orow + pos + 0, f.x * aval);
        atomicAdd(orow + pos + 1, f.y * aval);
        atomicAdd(orow + pos + 2, f.z * aval);
        atomicAdd(orow + pos + 3, f.w * aval);
    }
}

// ---------------- launch -----------------------------------------------------
extern "C" void kernel_launch(void* const* d_in, const int* in_sizes, int n_in,
                              void* d_out, int out_size) {
    const float* node_feat = (const float*)d_in[0];   // (N,128)
    const float* edge_feat = (const float*)d_in[1];   // (E,3,128)
    const float* W_enc     = (const float*)d_in[2];   // (128,512)
    const float* attn_l    = (const float*)d_in[3];   // (1,8,64)
    const float* W_r       = (const float*)d_in[4];   // (8,128)
    const int*   dst       = (const int*)d_in[5];     // (E,)
    float* out = (float*)d_out;                       // (N,8,64)

    zero_kernel<<<1024, 256>>>(out);
    er_kernel<<<NN / 8, 256>>>(node_feat, W_r);                 // 8 warps/block
    mean_kernel<<<(EE * (DD / 4) + 255) / 256, 256>>>((const float4*)edge_feat);
    gemm_kernel<<<dim3(KH / BN, EE / BM), 256>>>(W_enc);
    logits_kernel<<<EE / 8, 256>>>(attn_l, dst);                // 1 warp/edge
    scatter_kernel<<<EE / 8, 256>>>(dst, out);                  // 1 warp/edge
}

// round 3
// speedup vs baseline: 1.2339x; 1.2339x over previous
#include <cuda_runtime.h>
#include <cstdint>

#define NN 20000
#define EE 320000
#define DD 128
#define KK 8
#define HH 64
#define KH 512   // K*H

// GEMM tiling
#define BM 64
#define BN 256
#define AP 132   // A smem row stride (floats), pad 4 -> bank shift 4
#define BP 260   // B smem row stride (floats), pad 4 -> bank shift 4
#define SMEM_DYN ((BM * AP + DD * BP) * 4 + 2048 + 16)

// ---------------- scratch (static device arrays; no runtime allocation) ----
__device__ float g_ft[(size_t)EE * KH];       // encoded edge features
__device__ float g_ex[(size_t)EE * KK];       // exp(logits)
__device__ float g_er[(size_t)NN * KK];       // node_feat @ W_r^T
__device__ float g_segsum[(size_t)NN * KK];   // softmax denominators

// ---------------- helpers ---------------------------------------------------
__device__ __forceinline__ float to_tf32(float x) {
    float r;
    asm("cvt.rna.tf32.f32 %0, %1;" : "=f"(r) : "f"(x));
    return r;
}

__device__ __forceinline__ void mma_tf32(float* c, const uint32_t* a, const uint32_t* b) {
    asm volatile(
        "mma.sync.aligned.m16n8k8.row.col.f32.tf32.tf32.f32 "
        "{%0,%1,%2,%3}, {%4,%5,%6,%7}, {%8,%9}, {%0,%1,%2,%3};"
        : "+f"(c[0]), "+f"(c[1]), "+f"(c[2]), "+f"(c[3])
        : "r"(a[0]), "r"(a[1]), "r"(a[2]), "r"(a[3]), "r"(b[0]), "r"(b[1]));
}

// ---------------- zero out + segsum ----------------------------------------
__global__ void zero_kernel(float* __restrict__ out) {
    int stride = gridDim.x * blockDim.x;
    int i = blockIdx.x * blockDim.x + threadIdx.x;
    for (int t = i; t < NN * KH; t += stride) out[t] = 0.0f;
    for (int t = i; t < NN * KK; t += stride) g_segsum[t] = 0.0f;
}

// ---------------- er[n][k] = dot(node_feat[n], W_r[k]) ---------------------
__global__ void er_kernel(const float* __restrict__ nf, const float* __restrict__ Wr) {
    int warp = (blockIdx.x * blockDim.x + threadIdx.x) >> 5;
    int lane = threadIdx.x & 31;
    if (warp >= NN) return;
    float4 x = *(const float4*)(nf + (size_t)warp * DD + lane * 4);
#pragma unroll
    for (int k = 0; k < KK; k++) {
        float4 w = *(const float4*)(Wr + (size_t)k * DD + lane * 4);
        float p = x.x * w.x + x.y * w.y + x.z * w.z + x.w * w.w;
#pragma unroll
        for (int off = 16; off > 0; off >>= 1) p += __shfl_xor_sync(0xffffffffu, p, off);
        if (lane == 0) g_er[(size_t)warp * KK + k] = p;
    }
}

// ---------------- fused mean + tf32 mma GEMM + logits epilogue --------------
// C tile (64 x 256) = mean(edge_feat rows) @ W_enc cols.
// 8 warps as 2 (M) x 4 (N); each warp: 32 x 64 = one complete head.
__global__ __launch_bounds__(256, 1) void mma_gemm_kernel(
    const float* __restrict__ edge_feat, const float* __restrict__ W_enc,
    const float* __restrict__ attn_l, const int* __restrict__ dst) {
    extern __shared__ float sm[];
    float* As = sm;                  // [BM][AP]
    float* Bs = sm + BM * AP;        // [DD][BP]
    float* s_al = Bs + DD * BP;      // [KH]

    int t = threadIdx.x;
    int w = t >> 5, l = t & 31;
    int g = l >> 2, tig = l & 3;
    int warp_m = w >> 2, warp_n = w & 3;
    int bx = blockIdx.x;      // 0..1   (N halves)
    int by = blockIdx.y;      // 0..4999 (edge tiles of 64)

    for (int i = t; i < KH; i += 256) s_al[i] = attn_l[i];

    // ---- A tile: fused mean over L=3, cvt tf32, store to SMEM --------------
    {
        int r = w * 8 + (l >> 2);    // wrong stride; recompute below properly
    }
    // warp w owns rows w*8 .. w*8+7; lane handles one float4 column per row
    {
        for (int rr = 0; rr < 8; rr++) {
            int r = w * 8 + rr;
            size_t base = ((size_t)(by * BM + r)) * 3 * DD + l * 4;
            float4 a = *(const float4*)(edge_feat + base);
            float4 b = *(const float4*)(edge_feat + base + DD);
            float4 c = *(const float4*)(edge_feat + base + 2 * DD);
            const float s = 1.0f / 3.0f;
            float4 m;
            m.x = to_tf32((a.x + b.x + c.x) * s);
            m.y = to_tf32((a.y + b.y + c.y) * s);
            m.z = to_tf32((a.z + b.z + c.z) * s);
            m.w = to_tf32((a.w + b.w + c.w) * s);
            *(float4*)(As + r * AP + l * 4) = m;
        }
    }
    // ---- B tile: W_enc rows 0..127, cols [bx*256, +256) --------------------
    {
        int r = t >> 1;              // 0..127
        int half = t & 1;            // which 128-col half
        const float* src = W_enc + (size_t)r * KH + bx * BN + half * 128;
        float* dstp = Bs + r * BP + half * 128;
#pragma unroll
        for (int i = 0; i < 32; i++) {
            float4 v = *(const float4*)(src + i * 4);
            v.x = to_tf32(v.x); v.y = to_tf32(v.y);
            v.z = to_tf32(v.z); v.w = to_tf32(v.w);
            *(float4*)(dstp + i * 4) = v;
        }
    }
    __syncthreads();

    // ---- mma mainloop ------------------------------------------------------
    float c[2][8][4];
#pragma unroll
    for (int mi = 0; mi < 2; mi++)
#pragma unroll
        for (int j = 0; j < 8; j++)
#pragma unroll
            for (int q = 0; q < 4; q++) c[mi][j][q] = 0.0f;

    const uint32_t* Au = (const uint32_t*)As;
    const uint32_t* Bu = (const uint32_t*)Bs;
    int am_base = warp_m * 32;
    int bn_base = warp_n * 64;

#pragma unroll 4
    for (int kc = 0; kc < 16; kc++) {
        int k0 = kc * 8;
        uint32_t a[2][4];
#pragma unroll
        for (int mi = 0; mi < 2; mi++) {
            int rb = am_base + mi * 16;
            a[mi][0] = Au[(rb + g) * AP + k0 + tig];
            a[mi][1] = Au[(rb + g + 8) * AP + k0 + tig];
            a[mi][2] = Au[(rb + g) * AP + k0 + tig + 4];
            a[mi][3] = Au[(rb + g + 8) * AP + k0 + tig + 4];
        }
        uint32_t b[8][2];
#pragma unroll
        for (int j = 0; j < 8; j++) {
            int nb = bn_base + j * 8 + g;
            b[j][0] = Bu[(k0 + tig) * BP + nb];
            b[j][1] = Bu[(k0 + tig + 4) * BP + nb];
        }
#pragma unroll
        for (int mi = 0; mi < 2; mi++)
#pragma unroll
            for (int j = 0; j < 8; j++) mma_tf32(c[mi][j], a[mi], b[j]);
    }

    // ---- epilogue: store ft + fused logits ---------------------------------
    int k_head = bx * 4 + warp_n;
    int ha = k_head * HH;
    size_t ebase = (size_t)by * BM + am_base;

    // per-thread el accumulation: rows (mi,g) and (mi,g+8)
    float el0[2] = {0.0f, 0.0f};
    float el1[2] = {0.0f, 0.0f};
#pragma unroll
    for (int mi = 0; mi < 2; mi++)
#pragma unroll
        for (int j = 0; j < 8; j++) {
            int hcol = j * 8 + 2 * tig;
            float w0 = s_al[ha + hcol], w1 = s_al[ha + hcol + 1];
            el0[mi] += c[mi][j][0] * w0 + c[mi][j][1] * w1;
            el1[mi] += c[mi][j][2] * w0 + c[mi][j][3] * w1;
        }
    // quad reduce over tig
#pragma unroll
    for (int off = 1; off <= 2; off <<= 1) {
#pragma unroll
        for (int mi = 0; mi < 2; mi++) {
            el0[mi] += __shfl_xor_sync(0xffffffffu, el0[mi], off);
            el1[mi] += __shfl_xor_sync(0xffffffffu, el1[mi], off);
        }
    }
    if (tig == 0) {
#pragma unroll
        for (int mi = 0; mi < 2; mi++) {
#pragma unroll
            for (int h = 0; h < 2; h++) {
                size_t e = ebase + mi * 16 + h * 8 + g;
                int d = dst[e];
                float v = (h == 0 ? el0[mi] : el1[mi]) + g_er[(size_t)d * KK + k_head];
                v = (v > 0.0f) ? v : 0.01f * v;
                float exv = expf(v);
                g_ex[e * KK + k_head] = exv;
                atomicAdd(&g_segsum[(size_t)d * KK + k_head], exv);
            }
        }
    }
    // ft stores (float2 per (row, j))
#pragma unroll
    for (int mi = 0; mi < 2; mi++) {
        size_t e0 = ebase + mi * 16 + g;
        float* p0 = g_ft + e0 * KH + ha;
        float* p1 = g_ft + (e0 + 8) * KH + ha;
#pragma unroll
        for (int j = 0; j < 8; j++) {
            int hcol = j * 8 + 2 * tig;
            *(float2*)(p0 + hcol) = make_float2(c[mi][j][0], c[mi][j][1]);
            *(float2*)(p1 + hcol) = make_float2(c[mi][j][2], c[mi][j][3]);
        }
    }
}

// ---------------- weighted scatter into destination nodes -------------------
__global__ void scatter_kernel(const int* __restrict__ dst, float* __restrict__ out) {
    int wg = (blockIdx.x * blockDim.x + threadIdx.x) >> 5;
    int lane = threadIdx.x & 31;
    if (wg >= EE) return;
    int d = dst[wg];
    const float* row = g_ft + (size_t)wg * KH;
    float* orow = out + (size_t)d * KH;
#pragma unroll
    for (int c = 0; c < 4; c++) {
        int k = c * 2 + (lane >> 4);
        float aval = g_ex[(size_t)wg * KK + k] / g_segsum[(size_t)d * KK + k];
        int pos = c * 128 + lane * 4;
        float4 f = *(const float4*)(row + pos);
        atomicAdd(orow + pos + 0, f.x * aval);
        atomicAdd(orow + pos + 1, f.y * aval);
        atomicAdd(orow + pos + 2, f.z * aval);
        atomicAdd(orow + pos + 3, f.w * aval);
    }
}

// ---------------- launch -----------------------------------------------------
extern "C" void kernel_launch(void* const* d_in, const int* in_sizes, int n_in,
                              void* d_out, int out_size) {
    const float* node_feat = (const float*)d_in[0];   // (N,128)
    const float* edge_feat = (const float*)d_in[1];   // (E,3,128)
    const float* W_enc     = (const float*)d_in[2];   // (128,512)
    const float* attn_l    = (const float*)d_in[3];   // (1,8,64)
    const float* W_r       = (const float*)d_in[4];   // (8,128)
    const int*   dst       = (const int*)d_in[5];     // (E,)
    float* out = (float*)d_out;                       // (N,8,64)

    cudaFuncSetAttribute(mma_gemm_kernel,
                         cudaFuncAttributeMaxDynamicSharedMemorySize, SMEM_DYN);

    zero_kernel<<<1024, 256>>>(out);
    er_kernel<<<NN / 8, 256>>>(node_feat, W_r);
    mma_gemm_kernel<<<dim3(2, EE / BM), 256, SMEM_DYN>>>(edge_feat, W_enc, attn_l, dst);
    scatter_kernel<<<EE / 8, 256>>>(dst, out);
}

// round 4
// speedup vs baseline: 4.1658x; 3.3760x over previous
#include <cuda_runtime.h>
#include <cstdint>

#define NN 20000
#define EE 320000
#define DD 128
#define KK 8
#define HH 64
#define KH 512   // K*H

// ---------------- scratch (static device arrays) ----------------------------
__device__ float g_mean[(size_t)EE * DD];          // 164 MB mean features
__device__ float g_ex[(size_t)EE * KK];            // exp(logits)
__device__ float g_er[(size_t)NN * KK];            // node_feat @ W_r^T
__device__ float g_W2[KK * DD];                    // [k][d] reduced weights
__device__ float g_S[(size_t)NN * KK * DD];        // 82 MB aggregated
__device__ int   g_cnt[NN];
__device__ int   g_off[NN + 1];
__device__ int   g_cur[NN];
__device__ int   g_list[EE];

// ---------------- setup ------------------------------------------------------
__global__ void zero_cnt_kernel() {
    int i = blockIdx.x * blockDim.x + threadIdx.x;
    if (i < NN) g_cnt[i] = 0;
}

// W2[k][d] = sum_h W_enc[d, k*H+h] * attn_l[k*H+h]
__global__ void w2_kernel(const float* __restrict__ W_enc,
                          const float* __restrict__ attn_l) {
    int t = blockIdx.x * blockDim.x + threadIdx.x;   // 1024 threads
    if (t >= KK * DD) return;
    int d = t >> 3, k = t & 7;
    float s = 0.0f;
#pragma unroll 8
    for (int h = 0; h < HH; h++)
        s += W_enc[(size_t)d * KH + k * HH + h] * attn_l[k * HH + h];
    g_W2[k * DD + d] = s;
}

// ---------------- er[n][k] = dot(node_feat[n], W_r[k]) ----------------------
__global__ void er_kernel(const float* __restrict__ nf, const float* __restrict__ Wr) {
    int warp = (blockIdx.x * blockDim.x + threadIdx.x) >> 5;
    int lane = threadIdx.x & 31;
    if (warp >= NN) return;
    float4 x = *(const float4*)(nf + (size_t)warp * DD + lane * 4);
#pragma unroll
    for (int k = 0; k < KK; k++) {
        float4 w = *(const float4*)(Wr + (size_t)k * DD + lane * 4);
        float p = x.x * w.x + x.y * w.y + x.z * w.z + x.w * w.w;
#pragma unroll
        for (int off = 16; off > 0; off >>= 1) p += __shfl_xor_sync(0xffffffffu, p, off);
        if (lane == 0) g_er[(size_t)warp * KK + k] = p;
    }
}

// ---------------- CSR build --------------------------------------------------
__global__ void hist_kernel(const int* __restrict__ dst) {
    int e = blockIdx.x * blockDim.x + threadIdx.x;
    if (e < EE) atomicAdd(&g_cnt[dst[e]], 1);
}

__global__ void scan_kernel() {   // single block, 1024 threads, 20 counts each
    __shared__ int part[1024];
    int t = threadIdx.x;
    int base = t * 20;
    int loc[20];
    int s = 0;
#pragma unroll
    for (int i = 0; i < 20; i++) {
        int idx = base + i;
        int c = (idx < NN) ? g_cnt[idx] : 0;
        loc[i] = s;
        s += c;
    }
    part[t] = s;
    __syncthreads();
    for (int off = 1; off < 1024; off <<= 1) {
        int v = (t >= off) ? part[t - off] : 0;
        __syncthreads();
        part[t] += v;
        __syncthreads();
    }
    int excl = (t == 0) ? 0 : part[t - 1];
#pragma unroll
    for (int i = 0; i < 20; i++) {
        int idx = base + i;
        if (idx < NN) {
            g_off[idx] = excl + loc[i];
            g_cur[idx] = excl + loc[i];
        }
    }
    if (t == 1023) g_off[NN] = part[1023];
}

__global__ void fill_kernel(const int* __restrict__ dst) {
    int e = blockIdx.x * blockDim.x + threadIdx.x;
    if (e < EE) {
        int p = atomicAdd(&g_cur[dst[e]], 1);
        g_list[p] = e;
    }
}

// ---------------- mean + logits + exp (one warp per edge) --------------------
__global__ __launch_bounds__(256) void mean_logits_kernel(
    const float* __restrict__ ef, const int* __restrict__ dst) {
    __shared__ float w2s[KK * DD];
    int t = threadIdx.x;
    for (int i = t; i < KK * DD; i += 256) w2s[i] = g_W2[i];
    __syncthreads();

    int warp = blockIdx.x * 8 + (t >> 5);   // EE/8 blocks, always full
    int lane = t & 31;

    size_t base = (size_t)warp * 3 * DD + lane * 4;
    float4 a = *(const float4*)(ef + base);
    float4 b = *(const float4*)(ef + base + DD);
    float4 c = *(const float4*)(ef + base + 2 * DD);
    const float s = 1.0f / 3.0f;
    float4 m;
    m.x = (a.x + b.x + c.x) * s;
    m.y = (a.y + b.y + c.y) * s;
    m.z = (a.z + b.z + c.z) * s;
    m.w = (a.w + b.w + c.w) * s;
    *(float4*)(g_mean + (size_t)warp * DD + lane * 4) = m;

    float p[KK];
#pragma unroll
    for (int k = 0; k < KK; k++) {
        float4 w = *(const float4*)(w2s + k * DD + lane * 4);
        p[k] = m.x * w.x + m.y * w.y + m.z * w.z + m.w * w.w;
    }
#pragma unroll
    for (int off = 16; off > 0; off >>= 1)
#pragma unroll
        for (int k = 0; k < KK; k++) p[k] += __shfl_xor_sync(0xffffffffu, p[k], off);

    if (lane == 0) {
        int d = dst[warp];
        float4 er0 = *(const float4*)(g_er + (size_t)d * KK);
        float4 er1 = *(const float4*)(g_er + (size_t)d * KK + 4);
        float erv[8] = {er0.x, er0.y, er0.z, er0.w, er1.x, er1.y, er1.z, er1.w};
        float exv[8];
#pragma unroll
        for (int k = 0; k < KK; k++) {
            float v = p[k] + erv[k];
            v = (v > 0.0f) ? v : 0.01f * v;
            exv[k] = expf(v);
        }
        *(float4*)(g_ex + (size_t)warp * KK) = make_float4(exv[0], exv[1], exv[2], exv[3]);
        *(float4*)(g_ex + (size_t)warp * KK + 4) = make_float4(exv[4], exv[5], exv[6], exv[7]);
    }
}

// ---------------- per-node gather-aggregate (no atomics) ---------------------
// block = node; thread t: k = t>>5, d4 = t&31 owns S[n][k][d4*4..+3]
#define BATCH 8
__global__ __launch_bounds__(256) void aggregate_kernel() {
    __shared__ float ms[BATCH][DD];
    __shared__ float exs[BATCH][KK];
    int n = blockIdx.x;
    int t = threadIdx.x;
    int k = t >> 5, d4 = t & 31;
    int beg = g_off[n], end = g_off[n + 1];

    float4 acc = make_float4(0.f, 0.f, 0.f, 0.f);
    float exsum = 0.0f;

    for (int p = beg; p < end; p += BATCH) {
        int nb = end - p;
        if (nb > BATCH) nb = BATCH;
        int e_loc = t >> 5;                     // 0..7
        if (e_loc < nb) {
            int e = g_list[p + e_loc];
            *(float4*)&ms[e_loc][d4 * 4] =
                *(const float4*)(g_mean + (size_t)e * DD + d4 * 4);
        }
        if (t < nb * KK) {
            int el2 = t >> 3, kk = t & 7;
            int e = g_list[p + el2];
            exs[el2][kk] = g_ex[(size_t)e * KK + kk];
        }
        __syncthreads();
#pragma unroll 4
        for (int j = 0; j < nb; j++) {
            float ev = exs[j][k];
            float4 mv = *(const float4*)&ms[j][d4 * 4];
            acc.x += ev * mv.x; acc.y += ev * mv.y;
            acc.z += ev * mv.z; acc.w += ev * mv.w;
            exsum += ev;
        }
        __syncthreads();
    }
    float scale = (exsum > 0.0f) ? (1.0f / exsum) : 0.0f;
    acc.x *= scale; acc.y *= scale; acc.z *= scale; acc.w *= scale;
    *(float4*)(g_S + ((size_t)n * KK + k) * DD + d4 * 4) = acc;
}

// ---------------- final small GEMM: out[n,k,:] = S[n,k,:] @ W_enc[:,kH:kH+H] -
// block: 64 nodes x 1 head; 256 threads as 16x16, 4x4 microtile
#define CP 129   // S smem stride
#define WP 65    // W smem stride
#define SMEM_C ((64 * CP + DD * WP) * 4)
__global__ __launch_bounds__(256) void out_gemm_kernel(
    const float* __restrict__ W_enc, float* __restrict__ out) {
    extern __shared__ float smc[];
    float* Ss = smc;              // [64][CP]
    float* Ws = smc + 64 * CP;    // [DD][WP]

    int t = threadIdx.x;
    int n0 = blockIdx.x * 64;
    int k = blockIdx.y;

    // load W tile: W_enc[d][k*64+h]
#pragma unroll
    for (int i = 0; i < 32; i++) {
        int idx = i * 256 + t;         // 8192
        int d = idx >> 6, h = idx & 63;
        Ws[d * WP + h] = W_enc[(size_t)d * KH + k * HH + h];
    }
    // load S tile: rows n0..n0+63
#pragma unroll
    for (int i = 0; i < 32; i++) {
        int idx = i * 256 + t;
        int r = idx >> 7, d = idx & 127;
        int n = n0 + r;
        Ss[r * CP + d] = (n < NN) ? g_S[((size_t)n * KK + k) * DD + d] : 0.0f;
    }
    __syncthreads();

    int tx = t & 15, ty = t >> 4;
    float c[4][4];
#pragma unroll
    for (int i = 0; i < 4; i++)
#pragma unroll
        for (int j = 0; j < 4; j++) c[i][j] = 0.0f;

#pragma unroll 8
    for (int d = 0; d < DD; d++) {
        float av[4], bv[4];
#pragma unroll
        for (int i = 0; i < 4; i++) av[i] = Ss[(ty * 4 + i) * CP + d];
#pragma unroll
        for (int j = 0; j < 4; j++) bv[j] = Ws[d * WP + tx * 4 + j];
#pragma unroll
        for (int i = 0; i < 4; i++)
#pragma unroll
            for (int j = 0; j < 4; j++) c[i][j] += av[i] * bv[j];
    }

#pragma unroll
    for (int i = 0; i < 4; i++) {
        int n = n0 + ty * 4 + i;
        if (n < NN) {
            *(float4*)(out + (size_t)n * KH + k * HH + tx * 4) =
                make_float4(c[i][0], c[i][1], c[i][2], c[i][3]);
        }
    }
}

// ---------------- launch -----------------------------------------------------
extern "C" void kernel_launch(void* const* d_in, const int* in_sizes, int n_in,
                              void* d_out, int out_size) {
    const float* node_feat = (const float*)d_in[0];   // (N,128)
    const float* edge_feat = (const float*)d_in[1];   // (E,3,128)
    const float* W_enc     = (const float*)d_in[2];   // (128,512)
    const float* attn_l    = (const float*)d_in[3];   // (1,8,64)
    const float* W_r       = (const float*)d_in[4];   // (8,128)
    const int*   dst       = (const int*)d_in[5];     // (E,)
    float* out = (float*)d_out;                       // (N,8,64)

    cudaFuncSetAttribute(out_gemm_kernel,
                         cudaFuncAttributeMaxDynamicSharedMemorySize, SMEM_C);

    zero_cnt_kernel<<<(NN + 255) / 256, 256>>>();
    w2_kernel<<<4, 256>>>(W_enc, attn_l);
    er_kernel<<<NN / 8, 256>>>(node_feat, W_r);
    hist_kernel<<<EE / 256, 256>>>(dst);
    scan_kernel<<<1, 1024>>>();
    fill_kernel<<<EE / 256, 256>>>(dst);
    mean_logits_kernel<<<EE / 8, 256>>>(edge_feat, dst);
    aggregate_kernel<<<NN, 256>>>();
    out_gemm_kernel<<<dim3((NN + 63) / 64, KK), 256, SMEM_C>>>(W_enc, out);
}